// round 6
// baseline (speedup 1.0000x reference)
#include <cuda_runtime.h>
#include <cuda_bf16.h>
#include <cstdint>

// ---------------------------------------------------------------------------
// Problem constants
// ---------------------------------------------------------------------------
#define N_OBJ   384
#define IN_DIM  256
#define CLS_DIM 128
#define HID     512
#define OUT_DIM 256
#define NPAIR   (N_OBJ * N_OBJ)      // 147456
#define NTILE_M (NPAIR / 128)        // 1152
#define BN_EPS  1e-5f

// ---------------------------------------------------------------------------
// Pre-split bf16 hi/lo operand storage (packed chunk blocks).
// A-block (128 rows x 32 k): 8192 B hi + 8192 B lo = 16384 B
// B-block (256 rows x 32 k): 16384 B hi + 16384 B lo = 32768 B
// ---------------------------------------------------------------------------
__device__ __align__(16) uint8_t g_ClsS[(size_t)NTILE_M * 4 * 16384];   // 75.5 MB
__device__ __align__(16) uint8_t g_H2S [(size_t)NTILE_M * 16 * 16384];  // 302 MB
__device__ __align__(16) uint8_t g_W1S [8 * 32768];
__device__ __align__(16) uint8_t g_W2S [16 * 32768];
__device__ float g_P[N_OBJ * HID];
__device__ float g_Q[N_OBJ * HID];

// ---------------------------------------------------------------------------
// SMEM geometry: padded ldmatrix layout, row stride 80 B (conflict-free).
// Per buffer: A hi @0, A lo @10240, B hi @20480, B lo @40960  -> 61440 B
// Double-buffered -> 122880 B dynamic smem.
// ---------------------------------------------------------------------------
#define SROW     80
#define A_LO     10240
#define B_BASE   20480
#define B_LO     20480        // relative to B_BASE
#define BUF_SZ   61440
#define SM_TOT   122880

__device__ __forceinline__ uint32_t smem_u32(const void* p) {
    uint32_t a;
    asm("{ .reg .u64 t; cvta.to.shared.u64 t, %1; cvt.u32.u64 %0, t; }"
        : "=r"(a) : "l"(p));
    return a;
}
__device__ __forceinline__ void cp16(uint32_t dst, const void* src) {
    asm volatile("cp.async.cg.shared.global [%0], [%1], 16;"
        :: "r"(dst), "l"(src) : "memory");
}
#define CP_COMMIT() asm volatile("cp.async.commit_group;" ::: "memory")
#define CP_WAIT(n)  asm volatile("cp.async.wait_group %0;" :: "n"(n) : "memory")

__device__ __forceinline__ void ldsm4(uint32_t* r, uint32_t addr) {
    asm volatile("ldmatrix.sync.aligned.m8n8.x4.shared.b16 {%0,%1,%2,%3}, [%4];"
        : "=r"(r[0]), "=r"(r[1]), "=r"(r[2]), "=r"(r[3]) : "r"(addr));
}
__device__ __forceinline__ void mma16816(float* c, const uint32_t* a, const uint32_t* b) {
    asm volatile(
        "mma.sync.aligned.m16n8k16.row.col.f32.bf16.bf16.f32 "
        "{%0,%1,%2,%3}, {%4,%5,%6,%7}, {%8,%9}, {%0,%1,%2,%3};"
        : "+f"(c[0]), "+f"(c[1]), "+f"(c[2]), "+f"(c[3])
        : "r"(a[0]), "r"(a[1]), "r"(a[2]), "r"(a[3]), "r"(b[0]), "r"(b[1]));
}

// Split two f32 into packed bf16 hi and bf16 lo (residual) words.
__device__ __forceinline__ void split2(float x, float y, uint32_t& hi, uint32_t& lo) {
    __nv_bfloat16 hx = __float2bfloat16(x), hy = __float2bfloat16(y);
    float lx = x - __bfloat162float(hx);
    float ly = y - __bfloat162float(hy);
    __nv_bfloat16 ex = __float2bfloat16(lx), ey = __float2bfloat16(ly);
    hi = (uint32_t)__bfloat16_as_ushort(hx) | ((uint32_t)__bfloat16_as_ushort(hy) << 16);
    lo = (uint32_t)__bfloat16_as_ushort(ex) | ((uint32_t)__bfloat16_as_ushort(ey) << 16);
}

// ---------------------------------------------------------------------------
// cp.async fills: packed global block -> padded smem tile
// ---------------------------------------------------------------------------
__device__ __forceinline__ void fill_A(const uint8_t* g, uint32_t sm, int tid) {
    #pragma unroll
    for (int u = 0; u < 4; ++u) {
        int lin = tid + 256 * u;              // 0..1023
        int half = lin >> 9;                  // 0=hi, 1=lo
        int rem = lin & 511;
        int row = rem >> 2, q = rem & 3;
        cp16(sm + half * A_LO + row * SROW + q * 16,
             g + half * 8192 + row * 64 + q * 16);
    }
}
__device__ __forceinline__ void fill_B(const uint8_t* g, uint32_t sm, int tid) {
    #pragma unroll
    for (int u = 0; u < 8; ++u) {
        int lin = tid + 256 * u;              // 0..2047
        int half = lin >> 10;
        int rem = lin & 1023;
        int row = rem >> 2, q = rem & 3;
        cp16(sm + half * B_LO + row * SROW + q * 16,
             g + half * 16384 + row * 64 + q * 16);
    }
}

// ---------------------------------------------------------------------------
// One BK=32 chunk of split-3 bf16 MMAs. Warp tile 64x64 (2M x 4N warps).
// ---------------------------------------------------------------------------
__device__ __forceinline__ void mma_chunk64(
    uint32_t base, int lane, int wm, int wn, float acc[4][8][4])
{
    const int m0w = wm * 64, n0w = wn * 64;
    const int arow = (lane & 7) + ((lane >> 3) & 1) * 8;
    const int acol = (lane >> 4) << 3;
    const int brow = ((lane >> 4) << 3) + (lane & 7);
    const int bcol = ((lane >> 3) & 1) << 3;

    #pragma unroll
    for (int ks = 0; ks < 2; ++ks) {
        const int kk = ks * 16;
        uint32_t Ah[4][4], Al[4][4], Bh[16], Bl[16];
        #pragma unroll
        for (int mt = 0; mt < 4; ++mt) {
            uint32_t ad = base + (uint32_t)(m0w + 16 * mt + arow) * SROW + (acol + kk) * 2;
            ldsm4(Ah[mt], ad);
            ldsm4(Al[mt], ad + A_LO);
        }
        #pragma unroll
        for (int np = 0; np < 4; ++np) {
            uint32_t bd = base + B_BASE +
                (uint32_t)(n0w + 16 * np + brow) * SROW + (bcol + kk) * 2;
            ldsm4(&Bh[4 * np], bd);
            ldsm4(&Bl[4 * np], bd + B_LO);
        }
        #pragma unroll
        for (int mt = 0; mt < 4; ++mt)
            #pragma unroll
            for (int nt = 0; nt < 8; ++nt) {
                mma16816(acc[mt][nt], Ah[mt], &Bh[2 * nt]);   // hi*hi
                mma16816(acc[mt][nt], Ah[mt], &Bl[2 * nt]);   // hi*lo
                mma16816(acc[mt][nt], Al[mt], &Bh[2 * nt]);   // lo*hi
            }
    }
}

// Shared double-buffered mainloop (pure copy + ldsm + mma).
__device__ __forceinline__ void mainloop(
    const uint8_t* gA, const uint8_t* gB, int NC,
    uint32_t su, int tid, int lane, int wm, int wn, float acc[4][8][4])
{
    fill_A(gA, su, tid);
    fill_B(gB, su + B_BASE, tid);
    CP_COMMIT();
    for (int c = 0; c < NC; ++c) {
        if (c + 1 < NC) {
            uint32_t nb = su + ((c + 1) & 1) * BUF_SZ;
            fill_A(gA + (size_t)(c + 1) * 16384, nb, tid);
            fill_B(gB + (size_t)(c + 1) * 32768, nb + B_BASE, tid);
            CP_COMMIT();
            CP_WAIT(1);
        } else {
            CP_WAIT(0);
        }
        __syncthreads();
        mma_chunk64(su + (c & 1) * BUF_SZ, lane, wm, wn, acc);
        __syncthreads();
    }
}

// ---------------------------------------------------------------------------
// Prep: split cls into g_ClsS (and write cls through to output region).
// grid (1152, 4)
// ---------------------------------------------------------------------------
__global__ __launch_bounds__(256) void k_split_cls(
    const float* __restrict__ cls, float* __restrict__ outC)
{
    const int t = blockIdx.x, c = blockIdx.y, tid = threadIdx.x;
    const float* src = cls + (size_t)t * 128 * CLS_DIM + c * 32;
    float* wt = outC + (size_t)t * 128 * CLS_DIM + c * 32;
    uint8_t* blk = g_ClsS + ((size_t)t * 4 + c) * 16384;
    #pragma unroll
    for (int u = 0; u < 4; ++u) {
        int lin = tid + 256 * u;          // 0..1023 = 128 rows x 8 float4
        int row = lin >> 3, q = lin & 7;
        float4 v = *reinterpret_cast<const float4*>(src + (size_t)row * CLS_DIM + q * 4);
        *reinterpret_cast<float4*>(wt + (size_t)row * CLS_DIM + q * 4) = v;
        uint32_t h0, l0, h1, l1;
        split2(v.x, v.y, h0, l0);
        split2(v.z, v.w, h1, l1);
        *reinterpret_cast<uint2*>(blk + row * 64 + q * 8)        = make_uint2(h0, h1);
        *reinterpret_cast<uint2*>(blk + 8192 + row * 64 + q * 8) = make_uint2(l0, l1);
    }
}

// Prep: split W1c (8 blocks) and W2 (16 blocks). grid (24)
__global__ __launch_bounds__(256) void k_split_w(
    const float* __restrict__ W1, const float* __restrict__ W2)
{
    const int b = blockIdx.x, tid = threadIdx.x;
    const float* src;
    int ld;
    uint8_t* blk;
    if (b < 8) {
        int h = b >> 2, c = b & 3;
        src = W1 + (size_t)(h * 256) * 640 + 512 + c * 32;
        ld = 640;
        blk = g_W1S + (size_t)b * 32768;
    } else {
        int c = b - 8;
        src = W2 + c * 32;
        ld = 512;
        blk = g_W2S + (size_t)c * 32768;
    }
    #pragma unroll
    for (int u = 0; u < 8; ++u) {
        int lin = tid + 256 * u;          // 0..2047 = 256 rows x 8 float4
        int row = lin >> 3, q = lin & 7;
        float4 v = *reinterpret_cast<const float4*>(src + (size_t)row * ld + q * 4);
        uint32_t h0, l0, h1, l1;
        split2(v.x, v.y, h0, l0);
        split2(v.z, v.w, h1, l1);
        *reinterpret_cast<uint2*>(blk + row * 64 + q * 8)         = make_uint2(h0, h1);
        *reinterpret_cast<uint2*>(blk + 16384 + row * 64 + q * 8) = make_uint2(l0, l1);
    }
}

// ---------------------------------------------------------------------------
// GEMM1: H2S = split(BN(LeakyReLU(cls @ W1c^T + P[i] + Q[j])))   grid (1152, 2)
// CTA tile 128 x 256, NC = 4.
// ---------------------------------------------------------------------------
__global__ __launch_bounds__(256, 1) void k_gemm1(
    const float* __restrict__ gamma, const float* __restrict__ beta,
    const float* __restrict__ rm, const float* __restrict__ rv)
{
    extern __shared__ __align__(128) char sm[];
    const uint32_t su = smem_u32(sm);
    const int tid = threadIdx.x, lane = tid & 31, wid = tid >> 5;
    const int wm = wid & 1, wn = wid >> 1;
    const int tM = blockIdx.x, h = blockIdx.y;

    const uint8_t* gA = g_ClsS + (size_t)tM * 4 * 16384;
    const uint8_t* gB = g_W1S + (size_t)h * 4 * 32768;

    float acc[4][8][4] = {};
    mainloop(gA, gB, 4, su, tid, lane, wm, wn, acc);

    // Epilogue: +P[i]+Q[j], LeakyReLU, BN, split -> g_H2S
    const int m0 = tM * 128;
    const int nbase = h * 256 + wn * 64;
    float sc[8][2], sh[8][2];
    #pragma unroll
    for (int nt = 0; nt < 8; ++nt) {
        int n = nbase + 8 * nt + 2 * (lane & 3);
        #pragma unroll
        for (int e = 0; e < 2; ++e) {
            float s = gamma[n + e] * rsqrtf(rv[n + e] + BN_EPS);
            sc[nt][e] = s;
            sh[nt][e] = beta[n + e] - rm[n + e] * s;
        }
    }
    #pragma unroll
    for (int mt = 0; mt < 4; ++mt)
        #pragma unroll
        for (int rh = 0; rh < 2; ++rh) {
            int r = wm * 64 + 16 * mt + (lane >> 2) + 8 * rh;    // row in tile
            int p = m0 + r;
            int i = p / N_OBJ;
            int j = p - i * N_OBJ;
            const float* Pr = g_P + (size_t)i * HID;
            const float* Qr = g_Q + (size_t)j * HID;
            #pragma unroll
            for (int nt = 0; nt < 8; ++nt) {
                int n = nbase + 8 * nt + 2 * (lane & 3);
                float2 pv = *reinterpret_cast<const float2*>(Pr + n);
                float2 qv = *reinterpret_cast<const float2*>(Qr + n);
                float v0 = acc[mt][nt][2 * rh + 0] + pv.x + qv.x;
                float v1 = acc[mt][nt][2 * rh + 1] + pv.y + qv.y;
                v0 = (v0 >= 0.f) ? v0 : 0.01f * v0;
                v1 = (v1 >= 0.f) ? v1 : 0.01f * v1;
                float o0 = fmaf(v0, sc[nt][0], sh[nt][0]);
                float o1 = fmaf(v1, sc[nt][1], sh[nt][1]);
                uint32_t hi, lo;
                split2(o0, o1, hi, lo);
                int cH = n >> 5, cc = n & 31;
                uint8_t* blk = g_H2S + ((size_t)tM * 16 + cH) * 16384;
                *reinterpret_cast<uint32_t*>(blk + r * 64 + cc * 2) = hi;
                *reinterpret_cast<uint32_t*>(blk + 8192 + r * 64 + cc * 2) = lo;
            }
        }
}

// ---------------------------------------------------------------------------
// GEMM2: features_out = H2 @ W2^T + b2     grid (1152), CTA 128x256, NC=16
// ---------------------------------------------------------------------------
__global__ __launch_bounds__(256, 1) void k_gemm2(
    const float* __restrict__ b2, float* __restrict__ outF)
{
    extern __shared__ __align__(128) char sm[];
    const uint32_t su = smem_u32(sm);
    const int tid = threadIdx.x, lane = tid & 31, wid = tid >> 5;
    const int wm = wid & 1, wn = wid >> 1;
    const int tM = blockIdx.x;

    const uint8_t* gA = g_H2S + (size_t)tM * 16 * 16384;
    const uint8_t* gB = g_W2S;

    float acc[4][8][4] = {};
    mainloop(gA, gB, 16, su, tid, lane, wm, wn, acc);

    const int m0 = tM * 128;
    const int nbase = wn * 64;
    float bb[8][2];
    #pragma unroll
    for (int nt = 0; nt < 8; ++nt) {
        int n = nbase + 8 * nt + 2 * (lane & 3);
        bb[nt][0] = b2[n];
        bb[nt][1] = b2[n + 1];
    }
    #pragma unroll
    for (int mt = 0; mt < 4; ++mt)
        #pragma unroll
        for (int rh = 0; rh < 2; ++rh) {
            int p = m0 + wm * 64 + 16 * mt + (lane >> 2) + 8 * rh;
            #pragma unroll
            for (int nt = 0; nt < 8; ++nt) {
                int n = nbase + 8 * nt + 2 * (lane & 3);
                float2 o;
                o.x = acc[mt][nt][2 * rh + 0] + bb[nt][0];
                o.y = acc[mt][nt][2 * rh + 1] + bb[nt][1];
                *reinterpret_cast<float2*>(outF + (size_t)p * OUT_DIM + n) = o;
            }
        }
}

// ---------------------------------------------------------------------------
// P/Q precompute: fp32 register-blocked SGEMM (tiny: 0.2 GFLOP)
// ---------------------------------------------------------------------------
__device__ __forceinline__ void sgemm_tile(
    const float* __restrict__ A, int lda,
    const float* __restrict__ B, int ldb,
    int K, float acc[8][8], float* As, float* Bs, int tid)
{
    const int tx = tid & 15;
    const int ty = tid >> 4;
    for (int kt = 0; kt < K; kt += 16) {
        #pragma unroll
        for (int f = tid; f < 512; f += 256) {
            int row = f >> 2, kc = (f & 3) << 2;
            float4 v = *reinterpret_cast<const float4*>(A + (size_t)row * lda + kt + kc);
            As[(kc + 0) * 128 + row] = v.x; As[(kc + 1) * 128 + row] = v.y;
            As[(kc + 2) * 128 + row] = v.z; As[(kc + 3) * 128 + row] = v.w;
        }
        #pragma unroll
        for (int f = tid; f < 512; f += 256) {
            int row = f >> 2, kc = (f & 3) << 2;
            float4 v = *reinterpret_cast<const float4*>(B + (size_t)row * ldb + kt + kc);
            Bs[(kc + 0) * 128 + row] = v.x; Bs[(kc + 1) * 128 + row] = v.y;
            Bs[(kc + 2) * 128 + row] = v.z; Bs[(kc + 3) * 128 + row] = v.w;
        }
        __syncthreads();
        #pragma unroll
        for (int k = 0; k < 16; k++) {
            float4 a0 = *reinterpret_cast<const float4*>(As + k * 128 + ty * 8);
            float4 a1 = *reinterpret_cast<const float4*>(As + k * 128 + ty * 8 + 4);
            float4 b0 = *reinterpret_cast<const float4*>(Bs + k * 128 + tx * 8);
            float4 b1 = *reinterpret_cast<const float4*>(Bs + k * 128 + tx * 8 + 4);
            float a[8] = {a0.x, a0.y, a0.z, a0.w, a1.x, a1.y, a1.z, a1.w};
            float b[8] = {b0.x, b0.y, b0.z, b0.w, b1.x, b1.y, b1.z, b1.w};
            #pragma unroll
            for (int r = 0; r < 8; r++)
                #pragma unroll
                for (int c = 0; c < 8; c++)
                    acc[r][c] = fmaf(a[r], b[c], acc[r][c]);
        }
        __syncthreads();
    }
}

__global__ __launch_bounds__(256) void k_pq(
    const float* __restrict__ feats, const float* __restrict__ W1,
    const float* __restrict__ b1)
{
    __shared__ __align__(16) float As[16 * 128];
    __shared__ __align__(16) float Bs[16 * 128];
    float acc[8][8] = {};
    const int tid = threadIdx.x;
    const int z = blockIdx.z;
    const float* A = feats + (size_t)blockIdx.x * 128 * IN_DIM;
    const float* B = W1 + (size_t)blockIdx.y * 128 * 640 + z * 256;
    sgemm_tile(A, IN_DIM, B, 640, IN_DIM, acc, As, Bs, tid);

    const int tx = tid & 15, ty = tid >> 4;
    const int row0 = blockIdx.x * 128 + ty * 8;
    const int col0 = blockIdx.y * 128 + tx * 8;
    float* dst = z ? g_Q : g_P;
    #pragma unroll
    for (int r = 0; r < 8; r++) {
        float out[8];
        #pragma unroll
        for (int c = 0; c < 8; c++) {
            float add = z ? 0.f : b1[col0 + c];
            out[c] = acc[r][c] + add;
        }
        float4* d4 = reinterpret_cast<float4*>(dst + (size_t)(row0 + r) * HID + col0);
        d4[0] = make_float4(out[0], out[1], out[2], out[3]);
        d4[1] = make_float4(out[4], out[5], out[6], out[7]);
    }
}

// ---------------------------------------------------------------------------
// Attention tail — single pass over F with online softmax. One block per i.
// ---------------------------------------------------------------------------
__global__ __launch_bounds__(256) void k_attn(
    const float* __restrict__ F, const float* __restrict__ Wa,
    float* __restrict__ enh)
{
    __shared__ float wa_s[256];
    __shared__ float warp_m[8], warp_s[8];
    __shared__ float warp_acc[8][256];
    const int i = blockIdx.x;
    const int tid = threadIdx.x;
    const int w = tid >> 5, lane = tid & 31;
    wa_s[tid] = Wa[tid];
    __syncthreads();

    float m = -3.4e38f, sum = 0.f;
    float acc[8] = {};
    const float* base = F + (size_t)i * N_OBJ * OUT_DIM;
    for (int j = w; j < N_OBJ; j += 8) {
        const float* row = base + (size_t)j * OUT_DIM;
        float v[8];
        float dot = 0.f;
        #pragma unroll
        for (int k = 0; k < 8; k++) {
            v[k] = row[lane + 32 * k];
            dot = fmaf(v[k], wa_s[lane + 32 * k], dot);
        }
        #pragma unroll
        for (int o = 16; o; o >>= 1) dot += __shfl_xor_sync(0xffffffffu, dot, o);
        float mn = fmaxf(m, dot);
        float scale = expf(m - mn);
        float e = expf(dot - mn);
        sum = sum * scale + e;
        #pragma unroll
        for (int k = 0; k < 8; k++) acc[k] = fmaf(acc[k], scale, e * v[k]);
        m = mn;
    }
    if (lane == 0) { warp_m[w] = m; warp_s[w] = sum; }
    #pragma unroll
    for (int k = 0; k < 8; k++) warp_acc[w][lane + 32 * k] = acc[k];
    __syncthreads();

    float M = warp_m[0];
    #pragma unroll
    for (int q = 1; q < 8; q++) M = fmaxf(M, warp_m[q]);
    float S = 0.f, Ao = 0.f;
    #pragma unroll
    for (int q = 0; q < 8; q++) {
        float scq = expf(warp_m[q] - M);
        S = fmaf(warp_s[q], scq, S);
        Ao = fmaf(warp_acc[q][tid], scq, Ao);
    }
    enh[(size_t)i * OUT_DIM + tid] = Ao / S;
}

// ---------------------------------------------------------------------------
// Launch. Output layout: features_out | enhanced | classes_embedding
// ---------------------------------------------------------------------------
extern "C" void kernel_launch(void* const* d_in, const int* in_sizes, int n_in,
                              void* d_out, int out_size)
{
    const float* feats = (const float*)d_in[0];
    const float* cls   = (const float*)d_in[1];
    const float* W1    = (const float*)d_in[2];
    const float* b1    = (const float*)d_in[3];
    const float* gamma = (const float*)d_in[4];
    const float* beta  = (const float*)d_in[5];
    const float* rm    = (const float*)d_in[6];
    const float* rv    = (const float*)d_in[7];
    const float* W2    = (const float*)d_in[8];
    const float* b2    = (const float*)d_in[9];
    const float* Wa    = (const float*)d_in[10];
    // d_in[11] = ba: constant softmax shift, cancels

    float* out  = (float*)d_out;
    float* outF = out;
    float* outE = out + (size_t)NPAIR * OUT_DIM;
    float* outC = outE + (size_t)N_OBJ * OUT_DIM;

    static bool attr_set = false;
    if (!attr_set) {
        cudaFuncSetAttribute(k_gemm1, cudaFuncAttributeMaxDynamicSharedMemorySize, SM_TOT);
        cudaFuncSetAttribute(k_gemm2, cudaFuncAttributeMaxDynamicSharedMemorySize, SM_TOT);
        attr_set = true;
    }

    k_split_w<<<24, 256>>>(W1, W2);
    k_split_cls<<<dim3(NTILE_M, 4), 256>>>(cls, outC);
    k_pq<<<dim3(3, 4, 2), 256>>>(feats, W1, b1);
    k_gemm1<<<dim3(NTILE_M, 2), 256, SM_TOT>>>(gamma, beta, rm, rv);
    k_gemm2<<<NTILE_M, 256, SM_TOT>>>(b2, outF);
    k_attn<<<N_OBJ, 256>>>(outF, Wa, outE);
}